// round 11
// baseline (speedup 1.0000x reference)
#include <cuda_runtime.h>
#include <cuda_fp16.h>
#include <cstdint>

// GPTQ int4 dequant GEMM: out[M,N] = x[M,K] @ W[K,N].
// Stage 1: cvt_x_kernel: x f32 -> fp16 g_xh.
// Stage 2: dequant_w_kernel: qweight int4 -> fp16 g_wh[K,N].
// Stage 3: fp16 GEMM: 64x256x32 CTA tile, 256 thr (8 warps = 2m x 4n),
//          warp tile 32x64, mma.sync.m16n8k16, 5-stage smem ring,
//          prefetch depth 3 (wait_group 3), loads issued before wait (R9
//          discipline). 2 CTAs/SM. Aspect ratio chosen to balance smem
//          traffic (68KB/CTA-iter) against HMMA (512 cyc/CTA-iter).

#define Mdim 4096
#define Kdim 4096
#define Ndim 11008
#define BM 64
#define BN 256
#define BK 32
#define ALD 40                      // A smem row stride (halfs): 32 + 8 pad
#define BLD 264                     // B smem row stride (halfs): 256 + 8 pad
#define KTILES (Kdim / BK)          // 128
#define NST 5
#define ASTG2 (BM * ALD * 2)        // 5120 B
#define BSTG2 (BK * BLD * 2)        // 16896 B
#define DYN_SMEM (NST * (ASTG2 + BSTG2))   // 110080 B
#define NBLK (Ndim / BN)            // 43
#define MBLK (Mdim / BM)            // 64

__device__ __half g_xh[(size_t)Mdim * Kdim];   // 32 MB fp16 x
__device__ __half g_wh[(size_t)Kdim * Ndim];   // 90 MB fp16 W

__global__ __launch_bounds__(256)
void cvt_x_kernel(const float* __restrict__ x)
{
    size_t i = ((size_t)blockIdx.x * blockDim.x + threadIdx.x) * 8;
    float4 a = *(const float4*)(x + i);
    float4 b = *(const float4*)(x + i + 4);
    __half2 h[4];
    h[0] = __floats2half2_rn(a.x, a.y);
    h[1] = __floats2half2_rn(a.z, a.w);
    h[2] = __floats2half2_rn(b.x, b.y);
    h[3] = __floats2half2_rn(b.z, b.w);
    *(uint4*)(g_xh + i) = *(uint4*)h;
}

__global__ __launch_bounds__(256)
void dequant_w_kernel(const int*   __restrict__ qw,
                      const float* __restrict__ sc,
                      const int*   __restrict__ qz)
{
    const int n  = blockIdx.x * 256 + threadIdx.x;
    const int k8 = blockIdx.y;
    const int g  = k8 >> 4;

    const uint32_t q = (uint32_t)qw[(size_t)k8 * Ndim + n];
    const float sf = sc[(size_t)g * Ndim + n];
    const int qzw = qz[(size_t)g * (Ndim / 8) + (n >> 3)];
    const int z = ((qzw >> ((n & 7) * 4)) & 15) + 1;

    const __half sh = __float2half_rn(sf);
    const __half bh = __float2half_rn(1024.0f + (float)z);

    __half* w0 = g_wh + (size_t)(k8 * 8) * Ndim + n;
    #pragma unroll
    for (int j = 0; j < 8; j++) {
        uint32_t nib = ((q >> (4 * j)) & 15u) | 0x6400u;   // low lane = 1024+w
        __half hv = *(__half*)&nib;
        w0[(size_t)j * Ndim] = __hmul(__hsub(hv, bh), sh);
    }
}

__device__ __forceinline__ unsigned sptr(const void* p) {
    return (unsigned)__cvta_generic_to_shared(p);
}
__device__ __forceinline__ void cpa16(unsigned d, const void* s) {
    asm volatile("cp.async.cg.shared.global [%0], [%1], 16;\n" :: "r"(d), "l"(s));
}
__device__ __forceinline__ void cp_commit() { asm volatile("cp.async.commit_group;\n"); }
__device__ __forceinline__ void cp_wait3()  { asm volatile("cp.async.wait_group 3;\n"); }

__device__ __forceinline__ void ldmA(uint32_t r[4], unsigned a) {
    asm volatile("ldmatrix.sync.aligned.m8n8.x4.shared.b16 {%0,%1,%2,%3}, [%4];\n"
        : "=r"(r[0]), "=r"(r[1]), "=r"(r[2]), "=r"(r[3]) : "r"(a));
}
__device__ __forceinline__ void ldmBt(uint32_t r[4], unsigned a) {
    asm volatile("ldmatrix.sync.aligned.m8n8.x4.trans.shared.b16 {%0,%1,%2,%3}, [%4];\n"
        : "=r"(r[0]), "=r"(r[1]), "=r"(r[2]), "=r"(r[3]) : "r"(a));
}
__device__ __forceinline__ void mma16816(float c[4], const uint32_t a[4], const uint32_t b[2]) {
    asm volatile(
        "mma.sync.aligned.m16n8k16.row.col.f32.f16.f16.f32 "
        "{%0,%1,%2,%3}, {%4,%5,%6,%7}, {%8,%9}, {%0,%1,%2,%3};\n"
        : "+f"(c[0]), "+f"(c[1]), "+f"(c[2]), "+f"(c[3])
        : "r"(a[0]), "r"(a[1]), "r"(a[2]), "r"(a[3]), "r"(b[0]), "r"(b[1]));
}
__device__ __forceinline__ float r16(float v) {
    return __half2float(__float2half_rn(v));
}

__global__ __launch_bounds__(256, 2)
void gemm_kernel(float* __restrict__ out)
{
    extern __shared__ char smem[];
    const unsigned Abase = sptr(smem);
    const unsigned Bbase = Abase + NST * ASTG2;

    const int tid  = threadIdx.x;
    const int wid  = tid >> 5;
    const int lane = tid & 31;

    // ---- swizzled block mapping: groups of 8 m-blocks (B reuse in L2) ----
    const int id = blockIdx.x;
    const int GM = 8;
    const int group = id / (GM * NBLK);
    const int rem   = id % (GM * NBLK);
    const int mb = group * GM + (rem % GM);
    const int nb = rem / GM;
    const int m0 = mb * BM;
    const int n0 = nb * BN;

    // ---- A cp.async mapping: threads 0..63, one row each, 4x16B ----
    const int arow = tid & 63;
    const bool adoA = (tid < 64);
    const __half* gA = g_xh + (size_t)(m0 + arow) * Kdim;
    const unsigned sAo = Abase + (arow * ALD) * 2;

    // ---- B cp.async mapping: 8 threads/row, 32 halfs each (4x16B) ----
    const int brow  = tid >> 3;                    // 0..31 (k)
    const int bcolh = (tid & 7) << 5;              // 0..224 halfs
    const __half* gB = g_wh + (size_t)brow * Ndim + n0 + bcolh;   // + it*BK*Ndim
    const unsigned sBo = Bbase + (brow * BLD + bcolh) * 2;

    // ---- warp tiling: 2m x 4n, warp tile 32x64 ----
    const int wm = wid >> 2;                       // 0..1
    const int wn = wid & 3;                        // 0..3
    unsigned aB, bB;
    {
        const int l15 = lane & 15;
        const int hi8 = (lane >> 4) << 3;
        aB = Abase + ((wm * 32 + l15) * ALD + hi8) * 2;
        bB = Bbase + (l15 * BLD + wn * 64 + hi8) * 2;
    }

    float acc[2][8][4];
    #pragma unroll
    for (int mt = 0; mt < 2; mt++)
        #pragma unroll
        for (int nt = 0; nt < 8; nt++)
            #pragma unroll
            for (int i = 0; i < 4; i++) acc[mt][nt][i] = 0.f;

    auto load_tile = [&](int it, int stg) {
        if (adoA) {
            const unsigned da = sAo + stg * ASTG2;
            const __half* sa = gA + it * BK;
            #pragma unroll
            for (int u = 0; u < 4; u++)
                cpa16(da + u * 16, sa + u * 8);
        }
        const unsigned db = sBo + stg * BSTG2;
        const __half* sb = gB + (size_t)(it * BK) * Ndim;
        #pragma unroll
        for (int u = 0; u < 4; u++)
            cpa16(db + u * 16, sb + u * 8);
    };
    auto compute = [&](int stg) {
        const unsigned aS = aB + stg * ASTG2;
        const unsigned bS = bB + stg * BSTG2;
        #pragma unroll
        for (int ks = 0; ks < 2; ks++) {
            uint32_t a[2][4];
            #pragma unroll
            for (int mt = 0; mt < 2; mt++)
                ldmA(a[mt], aS + mt * (16 * ALD * 2) + ks * 32);
            uint32_t b[8][2];
            #pragma unroll
            for (int p = 0; p < 4; p++) {
                uint32_t r[4];
                ldmBt(r, bS + ks * (16 * BLD * 2) + p * 32);
                b[2 * p][0] = r[0]; b[2 * p][1] = r[1];
                b[2 * p + 1][0] = r[2]; b[2 * p + 1][1] = r[3];
            }
            #pragma unroll
            for (int mt = 0; mt < 2; mt++)
                #pragma unroll
                for (int nt = 0; nt < 8; nt++)
                    mma16816(acc[mt][nt], a[mt], b[nt]);
        }
    };

    // ---------------- prologue: tiles 0,1,2 in flight ----------------
    load_tile(0, 0); cp_commit();
    load_tile(1, 1); cp_commit();
    load_tile(2, 2); cp_commit();

    // ---------------- mainloop (R9 discipline) ----------------
    int s_cmp = 0, s_ld = 3;
    for (int it = 0; it < KTILES; ++it) {
        if (it + 3 < KTILES) load_tile(it + 3, s_ld);
        cp_commit();                      // one group per iter (maybe empty)
        cp_wait3();                       // tile `it` complete
        __syncthreads();
        compute(s_cmp);
        s_cmp = (s_cmp + 1 == NST) ? 0 : s_cmp + 1;
        s_ld  = (s_ld  + 1 == NST) ? 0 : s_ld  + 1;
    }

    // ---------------- epilogue ----------------
    const int r = lane >> 2;
    const int c = (lane & 3) << 1;
    #pragma unroll
    for (int mt = 0; mt < 2; mt++) {
        #pragma unroll
        for (int nt = 0; nt < 8; nt++) {
            const size_t row = (size_t)(m0 + wm * 32 + mt * 16 + r);
            const size_t col = (size_t)(n0 + wn * 64 + nt * 8 + c);
            float* p0 = out + row * Ndim + col;
            *(float2*)p0 = make_float2(r16(acc[mt][nt][0]), r16(acc[mt][nt][1]));
            *(float2*)(p0 + 8 * (size_t)Ndim) =
                make_float2(r16(acc[mt][nt][2]), r16(acc[mt][nt][3]));
        }
    }
}

extern "C" void kernel_launch(void* const* d_in, const int* in_sizes, int n_in,
                              void* d_out, int out_size)
{
    const float* x  = (const float*)d_in[0];
    const int*   qw = (const int*)d_in[1];
    const float* sc = (const float*)d_in[2];
    const int*   qz = (const int*)d_in[3];
    float* out = (float*)d_out;

    cvt_x_kernel<<<(Mdim * (size_t)Kdim) / (256 * 8), 256>>>(x);
    dequant_w_kernel<<<dim3(Ndim / 256, Kdim / 8), 256>>>(qw, sc, qz);

    cudaFuncSetAttribute(gemm_kernel,
                         cudaFuncAttributeMaxDynamicSharedMemorySize, DYN_SMEM);
    gemm_kernel<<<MBLK * NBLK, 256, DYN_SMEM>>>(out);
}

// round 13
// speedup vs baseline: 1.5643x; 1.5643x over previous
#include <cuda_runtime.h>
#include <cuda_fp16.h>
#include <cstdint>

// GPTQ int4 dequant GEMM: out[M,N] = x[M,K] @ W[K,N].
// Stage 1: cvt_x_kernel: x f32 -> fp16 g_xh.
// Stage 2: dequant_w_kernel: qweight int4 -> fp16 g_wh[K,N].
// Stage 3: fp16 GEMM: 128x128x32 CTA tile, 256 thr (8 warps = 4m x 2n),
//          warp tile 32x64, mma.sync.m16n8k16, 5-stage smem ring, prefetch
//          depth 3 (wait_group 3). Mainloop unrolled x5 (compile-time stages);
//          compute() software-pipelines register fragments (asm volatile order
//          guarantees ldsm issue ahead of use). 2 CTAs/SM. GM-swizzled grid.

#define Mdim 4096
#define Kdim 4096
#define Ndim 11008
#define BM 128
#define BN 128
#define BK 32
#define ALD 40                      // A smem row stride (halfs)
#define BLD 136                     // B smem row stride (halfs)
#define KTILES (Kdim / BK)          // 128
#define NST 5
#define ASTG2 (BM * ALD * 2)        // 10240 B
#define BSTG2 (BK * BLD * 2)        // 8704 B
#define DYN_SMEM (NST * (ASTG2 + BSTG2))   // 94720 B
#define NBLK (Ndim / BN)            // 86
#define MBLK (Mdim / BM)            // 32

__device__ __half g_xh[(size_t)Mdim * Kdim];   // 32 MB fp16 x
__device__ __half g_wh[(size_t)Kdim * Ndim];   // 90 MB fp16 W

__global__ __launch_bounds__(256)
void cvt_x_kernel(const float* __restrict__ x)
{
    size_t i = ((size_t)blockIdx.x * blockDim.x + threadIdx.x) * 8;
    float4 a = *(const float4*)(x + i);
    float4 b = *(const float4*)(x + i + 4);
    __half2 h[4];
    h[0] = __floats2half2_rn(a.x, a.y);
    h[1] = __floats2half2_rn(a.z, a.w);
    h[2] = __floats2half2_rn(b.x, b.y);
    h[3] = __floats2half2_rn(b.z, b.w);
    *(uint4*)(g_xh + i) = *(uint4*)h;
}

__global__ __launch_bounds__(256)
void dequant_w_kernel(const int*   __restrict__ qw,
                      const float* __restrict__ sc,
                      const int*   __restrict__ qz)
{
    const int n  = blockIdx.x * 256 + threadIdx.x;
    const int k8 = blockIdx.y;
    const int g  = k8 >> 4;

    const uint32_t q = (uint32_t)qw[(size_t)k8 * Ndim + n];
    const float sf = sc[(size_t)g * Ndim + n];
    const int qzw = qz[(size_t)g * (Ndim / 8) + (n >> 3)];
    const int z = ((qzw >> ((n & 7) * 4)) & 15) + 1;

    const __half sh = __float2half_rn(sf);
    const __half bh = __float2half_rn(1024.0f + (float)z);

    __half* w0 = g_wh + (size_t)(k8 * 8) * Ndim + n;
    #pragma unroll
    for (int j = 0; j < 8; j++) {
        uint32_t nib = ((q >> (4 * j)) & 15u) | 0x6400u;   // low lane = 1024+w
        __half hv = *(__half*)&nib;
        w0[(size_t)j * Ndim] = __hmul(__hsub(hv, bh), sh);
    }
}

__device__ __forceinline__ unsigned sptr(const void* p) {
    return (unsigned)__cvta_generic_to_shared(p);
}
__device__ __forceinline__ void cpa16(unsigned d, const void* s) {
    asm volatile("cp.async.cg.shared.global [%0], [%1], 16;\n" :: "r"(d), "l"(s));
}
__device__ __forceinline__ void cp_commit() { asm volatile("cp.async.commit_group;\n"); }
__device__ __forceinline__ void cp_wait3()  { asm volatile("cp.async.wait_group 3;\n"); }

__device__ __forceinline__ void ldmA(uint32_t r[4], unsigned a) {
    asm volatile("ldmatrix.sync.aligned.m8n8.x4.shared.b16 {%0,%1,%2,%3}, [%4];\n"
        : "=r"(r[0]), "=r"(r[1]), "=r"(r[2]), "=r"(r[3]) : "r"(a));
}
__device__ __forceinline__ void ldmBt(uint32_t r[4], unsigned a) {
    asm volatile("ldmatrix.sync.aligned.m8n8.x4.trans.shared.b16 {%0,%1,%2,%3}, [%4];\n"
        : "=r"(r[0]), "=r"(r[1]), "=r"(r[2]), "=r"(r[3]) : "r"(a));
}
__device__ __forceinline__ void mma16816(float c[4], const uint32_t a[4], const uint32_t b[2]) {
    asm volatile(
        "mma.sync.aligned.m16n8k16.row.col.f32.f16.f16.f32 "
        "{%0,%1,%2,%3}, {%4,%5,%6,%7}, {%8,%9}, {%0,%1,%2,%3};\n"
        : "+f"(c[0]), "+f"(c[1]), "+f"(c[2]), "+f"(c[3])
        : "r"(a[0]), "r"(a[1]), "r"(a[2]), "r"(a[3]), "r"(b[0]), "r"(b[1]));
}
__device__ __forceinline__ float r16(float v) {
    return __half2float(__float2half_rn(v));
}

__global__ __launch_bounds__(256, 2)
void gemm_kernel(float* __restrict__ out)
{
    extern __shared__ char smem[];
    const unsigned Abase = sptr(smem);
    const unsigned Bbase = Abase + NST * ASTG2;

    const int tid  = threadIdx.x;
    const int wid  = tid >> 5;
    const int lane = tid & 31;

    // ---- swizzled block mapping: groups of 8 m-blocks ----
    const int id = blockIdx.x;
    const int GM = 8;
    const int group = id / (GM * NBLK);
    const int rem   = id % (GM * NBLK);
    const int mb = group * GM + (rem % GM);
    const int nb = rem / GM;
    const int m0 = mb * BM;
    const int n0 = nb * BN;

    // ---- A cp.async mapping: row=tid>>1, 2x16B ----
    const int arow  = tid >> 1;
    const int acolh = (tid & 1) << 4;
    const __half* gA = g_xh + (size_t)(m0 + arow) * Kdim + acolh;
    const unsigned sAo = Abase + (arow * ALD + acolh) * 2;

    // ---- B cp.async mapping: row=tid>>3, 2x16B ----
    const int brow  = tid >> 3;
    const int bcolh = (tid & 7) << 4;
    const __half* gB = g_wh + (size_t)brow * Ndim + n0 + bcolh;
    const unsigned sBo = Bbase + (brow * BLD + bcolh) * 2;

    // ---- warp tiling: 4m x 2n, warp tile 32x64 ----
    const int wm = wid >> 1;
    const int wn = wid & 1;
    unsigned aB, bB;
    {
        const int l15 = lane & 15;
        const int hi8 = (lane >> 4) << 3;
        aB = Abase + ((wm * 32 + l15) * ALD + hi8) * 2;
        bB = Bbase + (l15 * BLD + wn * 64 + hi8) * 2;
    }

    float acc[2][8][4];
    #pragma unroll
    for (int mt = 0; mt < 2; mt++)
        #pragma unroll
        for (int nt = 0; nt < 8; nt++)
            #pragma unroll
            for (int i = 0; i < 4; i++) acc[mt][nt][i] = 0.f;

    auto load_tile = [&](int it, int stg) {
        const unsigned da = sAo + stg * ASTG2;
        const __half* sa = gA + it * BK;
        cpa16(da,      sa);
        cpa16(da + 16, sa + 8);
        const unsigned db = sBo + stg * BSTG2;
        const __half* sb = gB + (size_t)(it * BK) * Ndim;
        cpa16(db,      sb);
        cpa16(db + 16, sb + 8);
    };

    // Software-pipelined compute: asm volatile order = issue order.
    auto compute = [&](int stg) {
        const unsigned aS = aB + stg * ASTG2;
        const unsigned bS = bB + stg * BSTG2;
        uint32_t a0[2][4], a1[2][4], b0[8][2], b1[8][2];

        // issue ks0 frags + ks1 A frags
        ldmA(a0[0], aS);
        ldmA(a0[1], aS + 16 * ALD * 2);
        #pragma unroll
        for (int p = 0; p < 4; p++) {
            uint32_t r[4];
            ldmBt(r, bS + p * 32);
            b0[2 * p][0] = r[0]; b0[2 * p][1] = r[1];
            b0[2 * p + 1][0] = r[2]; b0[2 * p + 1][1] = r[3];
        }
        ldmA(a1[0], aS + 32);
        ldmA(a1[1], aS + 16 * ALD * 2 + 32);

        // ks0, mt=0 (8 mma) — covers ldsm above
        #pragma unroll
        for (int nt = 0; nt < 8; nt++)
            mma16816(acc[0][nt], a0[0], b0[nt]);

        // issue ks1 B frags — covered by remaining ks0 mmas
        #pragma unroll
        for (int p = 0; p < 4; p++) {
            uint32_t r[4];
            ldmBt(r, bS + 16 * BLD * 2 + p * 32);
            b1[2 * p][0] = r[0]; b1[2 * p][1] = r[1];
            b1[2 * p + 1][0] = r[2]; b1[2 * p + 1][1] = r[3];
        }

        // ks0, mt=1
        #pragma unroll
        for (int nt = 0; nt < 8; nt++)
            mma16816(acc[1][nt], a0[1], b0[nt]);

        // ks1, both mt
        #pragma unroll
        for (int mt = 0; mt < 2; mt++)
            #pragma unroll
            for (int nt = 0; nt < 8; nt++)
                mma16816(acc[mt][nt], a1[mt], b1[nt]);
    };

    // ---------------- prologue: tiles 0,1,2 in flight ----------------
    load_tile(0, 0); cp_commit();
    load_tile(1, 1); cp_commit();
    load_tile(2, 2); cp_commit();

    // ---------------- mainloop: 125 iters unrolled x5, stages compile-time ----
    #pragma unroll 1
    for (int base = 0; base < KTILES - 3; base += NST) {
        #pragma unroll
        for (int u = 0; u < NST; u++) {
            const int it = base + u;          // it % NST == u
            load_tile(it + 3, (u + 3) % NST); // it+3 <= 127 always here
            cp_commit();
            cp_wait3();
            __syncthreads();
            compute(u);
        }
    }
    // ---------------- tail: iters 125,126,127 (stages 0,1,2; no loads) ----
    #pragma unroll
    for (int u = 0; u < 3; u++) {
        cp_commit();                          // empty group keeps FIFO math
        cp_wait3();
        __syncthreads();
        compute(u);
    }

    // ---------------- epilogue ----------------
    const int r = lane >> 2;
    const int c = (lane & 3) << 1;
    #pragma unroll
    for (int mt = 0; mt < 2; mt++) {
        #pragma unroll
        for (int nt = 0; nt < 8; nt++) {
            const size_t row = (size_t)(m0 + wm * 32 + mt * 16 + r);
            const size_t col = (size_t)(n0 + wn * 64 + nt * 8 + c);
            float* p0 = out + row * Ndim + col;
            *(float2*)p0 = make_float2(r16(acc[mt][nt][0]), r16(acc[mt][nt][1]));
            *(float2*)(p0 + 8 * (size_t)Ndim) =
                make_float2(r16(acc[mt][nt][2]), r16(acc[mt][nt][3]));
        }
    }
}

extern "C" void kernel_launch(void* const* d_in, const int* in_sizes, int n_in,
                              void* d_out, int out_size)
{
    const float* x  = (const float*)d_in[0];
    const int*   qw = (const int*)d_in[1];
    const float* sc = (const float*)d_in[2];
    const int*   qz = (const int*)d_in[3];
    float* out = (float*)d_out;

    cvt_x_kernel<<<(Mdim * (size_t)Kdim) / (256 * 8), 256>>>(x);
    dequant_w_kernel<<<dim3(Ndim / 256, Kdim / 8), 256>>>(qw, sc, qz);

    cudaFuncSetAttribute(gemm_kernel,
                         cudaFuncAttributeMaxDynamicSharedMemorySize, DYN_SMEM);
    gemm_kernel<<<NBLK * MBLK, 256, DYN_SMEM>>>(out);
}